// round 3
// baseline (speedup 1.0000x reference)
#include <cuda_runtime.h>

// Problem constants
#define HH 512
#define WW 512
#define NB 8
#define CC 8
#define TILE 32
#define TPB 256
#define NTX 16            // tiles per dim
#define NBLOCKS (NTX*NTX*NB)   // 2048

// Gaussian 5-tap weights, sigma=2, normalized (computed in double at compile time)
static constexpr double E1d = 0.88249690258459546;  // exp(-1/8)
static constexpr double E2d = 0.60653065971263342;  // exp(-1/2)
static constexpr double GSd = 1.0 + 2.0 * (E1d + E2d);
static constexpr float GW0 = (float)(E2d / GSd);
static constexpr float GW1 = (float)(E1d / GSd);
static constexpr float GW2 = (float)(1.0 / GSd);

// Per-block partial sums (deterministic two-stage reduction; no allocs)
__device__ float g_part_ms[NBLOCKS];
__device__ float g_part_g[NBLOCKS];

__global__ __launch_bounds__(TPB)
void fused_loss_kernel(const float* __restrict__ pan,
                       const float* __restrict__ ms,
                       const float* __restrict__ out)
{
    // A: out channel tile with 2-halo (reflect-101), 36x36
    // B: horizontally blurred tile, 36 rows x 32 cols
    // M: channel-sum tile with 1-halo, 34x34
    // D: (mean - pan) diff tile with 1-halo (zero outside image), 34x34
    __shared__ float A[36 * 36];
    __shared__ float B[36 * 32];
    __shared__ float M[34 * 34];
    __shared__ float D[34 * 34];
    __shared__ float r_ms[8], r_g[8];

    const int tid = threadIdx.x;
    const int tx = tid & 31;
    const int ty = tid >> 5;
    const int n  = blockIdx.z;
    const int W0 = blockIdx.x * TILE;
    const int H0 = blockIdx.y * TILE;

    for (int i = tid; i < 34 * 34; i += TPB) M[i] = 0.f;

    float s_ms = 0.f;

    const float* outn = out + (size_t)n * CC * HH * WW;
    const float* msn  = ms  + (size_t)n * CC * HH * WW;

    for (int c = 0; c < CC; ++c) {
        const float* oc = outn + (size_t)c * HH * WW;
        __syncthreads();  // A/B safe to overwrite (also covers M zeroing on c==0)
        // Load 36x36 tile of out channel c with reflect-101 padding
        for (int i = tid; i < 36 * 36; i += TPB) {
            int r  = i / 36;
            int cl = i - r * 36;
            int h = H0 - 2 + r;
            h = h < 0 ? -h : (h >= HH ? 2 * (HH - 1) - h : h);
            int w = W0 - 2 + cl;
            w = w < 0 ? -w : (w >= WW ? 2 * (WW - 1) - w : w);
            A[i] = __ldg(&oc[h * WW + w]);
        }
        __syncthreads();
        // Horizontal Gaussian pass: B[36][32]
        for (int i = tid; i < 36 * 32; i += TPB) {
            int r  = i >> 5;
            int cl = i & 31;
            const float* a = &A[r * 36 + cl];
            B[i] = GW0 * a[0] + GW1 * a[1] + GW2 * a[2] + GW1 * a[3] + GW0 * a[4];
        }
        // Accumulate channel sum into M (34x34 inner region of A)
        for (int i = tid; i < 34 * 34; i += TPB) {
            int r  = i / 34;
            int cl = i - r * 34;
            M[i] += A[(r + 1) * 36 + (cl + 1)];
        }
        __syncthreads();
        // Vertical Gaussian pass + L1 vs ms (ms streamed coalesced from gmem)
        const float* mc = msn + (size_t)c * HH * WW;
        #pragma unroll
        for (int s = 0; s < 4; ++s) {
            int i = ty + 8 * s;
            float v = GW0 * B[(i    ) * 32 + tx]
                    + GW1 * B[(i + 1) * 32 + tx]
                    + GW2 * B[(i + 2) * 32 + tx]
                    + GW1 * B[(i + 3) * 32 + tx]
                    + GW0 * B[(i + 4) * 32 + tx];
            s_ms += fabsf(v - __ldg(&mc[(H0 + i) * WW + W0 + tx]));
        }
    }
    __syncthreads();
    // Build D = mean(out) - pan, zero where outside the image (Sobel zero-pad).
    // Sobel is linear with zero padding, so |sobel(mean)-sobel(pan)| = |sobel(D)|.
    const float* pn = pan + (size_t)n * HH * WW;
    for (int i = tid; i < 34 * 34; i += TPB) {
        int r  = i / 34;
        int cl = i - r * 34;
        int h = H0 - 1 + r;
        int w = W0 - 1 + cl;
        float dv = 0.f;
        if (h >= 0 && h < HH && w >= 0 && w < WW)
            dv = M[i] * 0.125f - __ldg(&pn[h * WW + w]);
        D[i] = dv;
    }
    __syncthreads();
    // 3x3 Sobel (cross-correlation, matching XLA conv) on D
    float s_g = 0.f;
    #pragma unroll
    for (int s = 0; s < 4; ++s) {
        int i = ty + 8 * s;
        const float* d0 = &D[(i    ) * 34 + tx];
        const float* d1 = &D[(i + 1) * 34 + tx];
        const float* d2 = &D[(i + 2) * 34 + tx];
        float t00 = d0[0], t01 = d0[1], t02 = d0[2];
        float t10 = d1[0],              t12 = d1[2];
        float t20 = d2[0], t21 = d2[1], t22 = d2[2];
        float gx = (t02 - t00) + 2.f * (t12 - t10) + (t22 - t20);
        float gy = (t20 - t00) + 2.f * (t21 - t01) + (t22 - t02);
        s_g += fabsf(gx) + fabsf(gy);
    }

    // Block reduction (deterministic within block)
    #pragma unroll
    for (int off = 16; off; off >>= 1) {
        s_ms += __shfl_down_sync(0xFFFFFFFFu, s_ms, off);
        s_g  += __shfl_down_sync(0xFFFFFFFFu, s_g,  off);
    }
    if (tx == 0) { r_ms[ty] = s_ms; r_g[ty] = s_g; }
    __syncthreads();
    if (tid == 0) {
        float a = 0.f, b = 0.f;
        #pragma unroll
        for (int k = 0; k < 8; ++k) { a += r_ms[k]; b += r_g[k]; }
        const int bid = (blockIdx.z * gridDim.y + blockIdx.y) * gridDim.x + blockIdx.x;
        g_part_ms[bid] = a;
        g_part_g[bid]  = b;
    }
}

__global__ __launch_bounds__(256)
void final_reduce_kernel(float* __restrict__ outp)
{
    __shared__ double sm[8], sg[8];
    const int tid = threadIdx.x;
    double a = 0.0, b = 0.0;
    for (int i = tid; i < NBLOCKS; i += 256) {
        a += (double)g_part_ms[i];
        b += (double)g_part_g[i];
    }
    #pragma unroll
    for (int off = 16; off; off >>= 1) {
        a += __shfl_down_sync(0xFFFFFFFFu, a, off);
        b += __shfl_down_sync(0xFFFFFFFFu, b, off);
    }
    if ((tid & 31) == 0) { sm[tid >> 5] = a; sg[tid >> 5] = b; }
    __syncthreads();
    if (tid == 0) {
        double ta = 0.0, tb = 0.0;
        #pragma unroll
        for (int k = 0; k < 8; ++k) { ta += sm[k]; tb += sg[k]; }
        const double inv_ms = 1.0 / ((double)NB * CC * HH * WW);
        const double inv_g  = 1.0 / ((double)NB * HH * WW);
        outp[0] = (float)(ta * inv_ms + tb * inv_g);
    }
}

extern "C" void kernel_launch(void* const* d_in, const int* in_sizes, int n_in,
                              void* d_out, int out_size)
{
    const float* pan = (const float*)d_in[0];  // [8,1,512,512]
    const float* ms  = (const float*)d_in[1];  // [8,8,512,512]
    const float* out = (const float*)d_in[2];  // [8,8,512,512]

    dim3 grid(NTX, NTX, NB);
    fused_loss_kernel<<<grid, TPB>>>(pan, ms, out);
    final_reduce_kernel<<<1, 256>>>((float*)d_out);
}

// round 4
// speedup vs baseline: 1.3636x; 1.3636x over previous
#include <cuda_runtime.h>
#include <cstdint>

#define HH 512
#define WW 512
#define NB 8
#define CC 8
#define TW 64
#define TH 32
#define TPB 256
#define GX (WW/TW)            // 8
#define GY (HH/TH)            // 16
#define NBLOCKS (GX*GY*NB)    // 1024

// A tile: rows h = H0-2 .. H0+33 (36), cols w = W0-4 .. W0+67 (72, 16B-aligned)
#define AH 36
#define AW 72
#define ASEG (AW/4)           // 18 16-byte segments per row
#define MW 68                 // M/D tile width (logical cols -1..66; only -1..64 used)

// Gaussian 5-tap weights, sigma=2 (exact, compile-time double)
static constexpr double E1d = 0.88249690258459546;  // exp(-1/8)
static constexpr double E2d = 0.60653065971263342;  // exp(-1/2)
static constexpr double GSd = 1.0 + 2.0 * (E1d + E2d);
static constexpr float GW0 = (float)(E2d / GSd);
static constexpr float GW1 = (float)(E1d / GSd);
static constexpr float GW2 = (float)(1.0 / GSd);

__device__ float g_pm[NBLOCKS];
__device__ float g_pg[NBLOCKS];
__device__ unsigned int g_count = 0;

__device__ __forceinline__ void cp16(uint32_t dst, const float* src) {
    asm volatile("cp.async.ca.shared.global [%0], [%1], 16;\n" :: "r"(dst), "l"(src));
}
__device__ __forceinline__ void cp_commit() {
    asm volatile("cp.async.commit_group;\n" ::: "memory");
}
__device__ __forceinline__ void cp_wait_all() {
    asm volatile("cp.async.wait_group 0;\n" ::: "memory");
}

__global__ __launch_bounds__(TPB)
void fused_loss_kernel(const float* __restrict__ pan,
                       const float* __restrict__ ms,
                       const float* __restrict__ out,
                       float* __restrict__ outp)
{
    __shared__ __align__(16) float A[2][AH][AW];  // out channel tile, double buffered
    __shared__ float B[AH][TW];                   // horizontally blurred
    __shared__ float M[TH + 2][MW];               // channel sum (later reused as diff D)
    __shared__ float r_ms[8], r_g[8];
    __shared__ double sm[8], sg[8];
    __shared__ bool s_last;

    const int tid = threadIdx.x;
    const int tx = tid & 31;
    const int ty = tid >> 5;
    const int n  = blockIdx.z;
    const int W0 = blockIdx.x * TW;
    const int H0 = blockIdx.y * TH;

    const float* outn = out + (size_t)n * CC * HH * WW;
    const float* msn  = ms  + (size_t)n * CC * HH * WW;

    for (int i = tid; i < (TH + 2) * MW; i += TPB) (&M[0][0])[i] = 0.f;

    const uint32_t aBase = (uint32_t)__cvta_generic_to_shared(&A[0][0][0]);

    // Issue async loads of out-channel c into buffer b.
    // Row reflection (reflect-101) is folded into the gmem source row.
    // Column reflection is fixed up in smem afterwards (only at W edges).
    auto issue_ch = [&](int c, int b) {
        const float* oc = outn + (size_t)c * HH * WW;
        for (int i = tid; i < AH * ASEG; i += TPB) {
            int r   = i / ASEG;
            int sgn = i - r * ASEG;
            int h = H0 - 2 + r;
            h = h < 0 ? -h : (h >= HH ? 2 * (HH - 1) - h : h);
            int w = W0 - 4 + sgn * 4;
            if (w >= 0 && w < WW)
                cp16(aBase + (uint32_t)(((b * AH + r) * AW + sgn * 4) * 4),
                     oc + (size_t)h * WW + w);
        }
        cp_commit();
    };

    issue_ch(0, 0);

    float s_ms = 0.f;
    float msreg[8];

    for (int c = 0; c < CC; ++c) {
        const int b = c & 1;
        cp_wait_all();
        __syncthreads();
        if (c + 1 < CC) issue_ch(c + 1, b ^ 1);

        // Prefetch ms values for this channel (coalesced, consumed in V pass)
        {
            const float* mc = msn + (size_t)c * HH * WW;
            #pragma unroll
            for (int s = 0; s < 4; ++s) {
                int i = ty + 8 * s;
                msreg[2 * s]     = __ldg(&mc[(size_t)(H0 + i) * WW + W0 + tx]);
                msreg[2 * s + 1] = __ldg(&mc[(size_t)(H0 + i) * WW + W0 + 32 + tx]);
            }
        }

        // Column reflect-101 fixup at image W edges (array col a <-> w = W0-4+a)
        if (W0 == 0) {
            for (int r = tid; r < AH; r += TPB) { A[b][r][2] = A[b][r][6]; A[b][r][3] = A[b][r][5]; }
        } else if (W0 == WW - TW) {
            for (int r = tid; r < AH; r += TPB) { A[b][r][68] = A[b][r][66]; A[b][r][69] = A[b][r][65]; }
        }
        __syncthreads();

        // Horizontal Gaussian pass: B[r][cl], logical col cl (array col cl+4)
        for (int i = tid; i < AH * TW; i += TPB) {
            int r = i >> 6, cl = i & 63;
            const float* a = &A[b][r][cl + 2];
            B[r][cl] = GW0 * a[0] + GW1 * a[1] + GW2 * a[2] + GW1 * a[3] + GW0 * a[4];
        }
        // Channel-sum accumulate: M row r <-> h = H0-1+r, col cl <-> w = W0-1+cl
        for (int i = tid; i < (TH + 2) * MW; i += TPB) {
            int r = i / MW, cl = i - r * MW;
            M[r][cl] += A[b][r + 1][cl + 3];
        }
        __syncthreads();

        // Vertical Gaussian pass + L1 vs ms
        #pragma unroll
        for (int s = 0; s < 4; ++s) {
            int i = ty + 8 * s;
            #pragma unroll
            for (int half = 0; half < 2; ++half) {
                int cl = tx + 32 * half;
                float v = GW0 * B[i][cl] + GW1 * B[i + 1][cl] + GW2 * B[i + 2][cl]
                        + GW1 * B[i + 3][cl] + GW0 * B[i + 4][cl];
                s_ms += fabsf(v - msreg[2 * s + half]);
            }
        }
    }
    __syncthreads();

    // D = mean(out) - pan in place over M; zero outside image (Sobel zero-pad).
    // |sobel(mean)-sobel(pan)| = |sobel(mean-pan)| by linearity.
    const float* pn = pan + (size_t)n * HH * WW;
    for (int i = tid; i < (TH + 2) * MW; i += TPB) {
        int r = i / MW, cl = i - r * MW;
        int h = H0 - 1 + r, w = W0 - 1 + cl;
        float dv = 0.f;
        if (h >= 0 && h < HH && w >= 0 && w < WW && cl < 66)
            dv = M[r][cl] * 0.125f - __ldg(&pn[(size_t)h * WW + w]);
        M[r][cl] = dv;
    }
    __syncthreads();

    // 3x3 Sobel (cross-correlation) on D
    float s_g = 0.f;
    #pragma unroll
    for (int s = 0; s < 4; ++s) {
        int i = ty + 8 * s;
        #pragma unroll
        for (int half = 0; half < 2; ++half) {
            int c0 = tx + 32 * half;
            float t00 = M[i][c0],     t01 = M[i][c0 + 1],     t02 = M[i][c0 + 2];
            float t10 = M[i + 1][c0],                         t12 = M[i + 1][c0 + 2];
            float t20 = M[i + 2][c0], t21 = M[i + 2][c0 + 1], t22 = M[i + 2][c0 + 2];
            float gx = (t02 - t00) + 2.f * (t12 - t10) + (t22 - t20);
            float gy = (t20 - t00) + 2.f * (t21 - t01) + (t22 - t02);
            s_g += fabsf(gx) + fabsf(gy);
        }
    }

    // Block reduction
    #pragma unroll
    for (int off = 16; off; off >>= 1) {
        s_ms += __shfl_down_sync(0xFFFFFFFFu, s_ms, off);
        s_g  += __shfl_down_sync(0xFFFFFFFFu, s_g,  off);
    }
    if (tx == 0) { r_ms[ty] = s_ms; r_g[ty] = s_g; }
    __syncthreads();

    const int bid = (blockIdx.z * gridDim.y + blockIdx.y) * gridDim.x + blockIdx.x;
    if (tid == 0) {
        float a = 0.f, bb = 0.f;
        #pragma unroll
        for (int k = 0; k < 8; ++k) { a += r_ms[k]; bb += r_g[k]; }
        g_pm[bid] = a;
        g_pg[bid] = bb;
        __threadfence();
        unsigned int old = atomicAdd(&g_count, 1);
        s_last = (old == NBLOCKS - 1);
    }
    __syncthreads();

    // Last arriving block performs the deterministic final reduction.
    if (s_last) {
        double a = 0.0, bb = 0.0;
        for (int i = tid; i < NBLOCKS; i += TPB) {
            a  += (double)g_pm[i];
            bb += (double)g_pg[i];
        }
        #pragma unroll
        for (int off = 16; off; off >>= 1) {
            a  += __shfl_down_sync(0xFFFFFFFFu, a,  off);
            bb += __shfl_down_sync(0xFFFFFFFFu, bb, off);
        }
        if (tx == 0) { sm[ty] = a; sg[ty] = bb; }
        __syncthreads();
        if (tid == 0) {
            double ta = 0.0, tb = 0.0;
            #pragma unroll
            for (int k = 0; k < 8; ++k) { ta += sm[k]; tb += sg[k]; }
            const double inv_ms = 1.0 / ((double)NB * CC * HH * WW);
            const double inv_g  = 1.0 / ((double)NB * HH * WW);
            outp[0] = (float)(ta * inv_ms + tb * inv_g);
            g_count = 0;  // reset for next (graph-replayed) launch
        }
    }
}

extern "C" void kernel_launch(void* const* d_in, const int* in_sizes, int n_in,
                              void* d_out, int out_size)
{
    const float* pan = (const float*)d_in[0];  // [8,1,512,512]
    const float* ms  = (const float*)d_in[1];  // [8,8,512,512]
    const float* out = (const float*)d_in[2];  // [8,8,512,512]

    dim3 grid(GX, GY, NB);
    fused_loss_kernel<<<grid, TPB>>>(pan, ms, out, (float*)d_out);
}